// round 6
// baseline (speedup 1.0000x reference)
#include <cuda_runtime.h>
#include <cuda_fp16.h>
#include <stdint.h>
#include <string.h>

#define N_PTS 2048
#define M_PTS 512
#define HID   128
#define TJ    64                  // j's per chunk
#define JT    (M_PTS / TJ)        // 8 chunks per i
#define NCHUNK (N_PTS * JT)       // 16384
#define NCTA  296                 // 2 per SM
#define PI_F  3.14159265358979323846f

// smem pitch: 136 fp16 per row = 272 B = 17 x 16B -> ldmatrix conflict-free
#define PITCH_B 272
#define H1_BUF_B 34816            // one h1 buffer: hi 17408 + lo 17408

// ---- shared memory layout (bytes) ----
#define SM_W2HI  0                      // [128][136] fp16 (W2^T hi) 34816 B
#define SM_H1    34816                  // 2 buffers x 34816
#define SM_B2W3  104448                 // 128 x float2
#define SM_YS    105472                 // 2 x 64 floats (y prefetch)
#define SM_RED   105984                 // 8 floats
#define SMEM_TOTAL 106112

// ---- device scratch ----
__device__ __align__(16) float g_A[N_PTS * HID];
__device__ __align__(16) float g_B[M_PTS * HID];
__device__ __align__(16) float g_y[M_PTS];
__device__ float g_Y;
__device__ __align__(16) float g_part[NCHUNK];

// ---------------------------------------------------------------------------
__device__ __forceinline__ float tanh_fast(float x) {
    float e = __expf(2.0f * x);
    return 1.0f - __fdividef(2.0f, e + 1.0f);
}

__device__ __forceinline__ uint32_t smem_u32(const void* p) {
    uint32_t a;
    asm("{ .reg .u64 t; cvta.to.shared.u64 t, %1; cvt.u32.u64 %0, t; }"
        : "=r"(a) : "l"(p));
    return a;
}

__device__ __forceinline__ void ldsm4(uint32_t& r0, uint32_t& r1,
                                      uint32_t& r2, uint32_t& r3, uint32_t addr) {
    asm volatile("ldmatrix.sync.aligned.m8n8.x4.shared.b16 {%0,%1,%2,%3}, [%4];"
                 : "=r"(r0), "=r"(r1), "=r"(r2), "=r"(r3) : "r"(addr));
}

__device__ __forceinline__ void mma_f16(float* d, const uint32_t* a,
                                        const uint32_t* b) {
    asm volatile(
        "mma.sync.aligned.m16n8k16.row.col.f32.f16.f16.f32 "
        "{%0,%1,%2,%3}, {%4,%5,%6,%7}, {%8,%9}, {%0,%1,%2,%3};"
        : "+f"(d[0]), "+f"(d[1]), "+f"(d[2]), "+f"(d[3])
        : "r"(a[0]), "r"(a[1]), "r"(a[2]), "r"(a[3]), "r"(b[0]), "r"(b[1]));
}

__device__ __forceinline__ uint32_t h2u(__half2 h) {
    uint32_t u; memcpy(&u, &h, 4); return u;
}

// fp32 pair -> packed fp16 hi + packed fp16 lo (residual)
__device__ __forceinline__ void split2h(float v0, float v1,
                                        uint32_t& hi, uint32_t& lo) {
    __half2 h = __floats2half2_rn(v0, v1);
    float2 hf = __half22float2(h);
    __half2 l = __floats2half2_rn(v0 - hf.x, v1 - hf.y);
    hi = h2u(h); lo = h2u(l);
}

// ---------------------------------------------------------------------------
__global__ void prep_ab_kernel(const float* __restrict__ inp,
                               const float* __restrict__ qx,
                               const float* __restrict__ W1,
                               const float* __restrict__ b1) {
    int idx = blockIdx.x * blockDim.x + threadIdx.x;
    const float4* W14 = (const float4*)W1;
    if (idx < N_PTS * 32) {
        int n = idx >> 5, v = idx & 31;
        float x0 = inp[2 * n], x1 = inp[2 * n + 1];
        float4 wa = W14[v], wb = W14[32 + v];
        float4 r;
        r.x = x0 * wa.x + x1 * wb.x;
        r.y = x0 * wa.y + x1 * wb.y;
        r.z = x0 * wa.z + x1 * wb.z;
        r.w = x0 * wa.w + x1 * wb.w;
        ((float4*)g_A)[idx] = r;
    } else {
        int t = idx - N_PTS * 32;
        if (t < M_PTS * 32) {
            int m = t >> 5, v = t & 31;
            float q0 = qx[2 * m], q1 = qx[2 * m + 1];
            float4 wc = W14[64 + v], wd = W14[96 + v];
            float4 bb = ((const float4*)b1)[v];
            float4 r;
            r.x = q0 * wc.x + q1 * wd.x + bb.x;
            r.y = q0 * wc.y + q1 * wd.y + bb.y;
            r.z = q0 * wc.z + q1 * wd.z + bb.z;
            r.w = q0 * wc.w + q1 * wd.w + bb.w;
            ((float4*)g_B)[t] = r;
        }
    }
}

__global__ void prep_y_kernel(const float* __restrict__ qx,
                              const float* __restrict__ ep) {
    __shared__ float red[512];
    int j = threadIdx.x;
    float e = ep[0];
    float y = sinf(PI_F * e * qx[2 * j]) * sinf(PI_F * e * qx[2 * j + 1]);
    g_y[j] = y;
    red[j] = y;
    __syncthreads();
    for (int s = 256; s > 0; s >>= 1) {
        if (j < s) red[j] += red[j + s];
        __syncthreads();
    }
    if (j == 0) g_Y = red[0];
}

// ---------------------------------------------------------------------------
// One eighth of phase 1 for chunk `cid` (warp wid handles row ks*8+wid).
// Also prefetches y into ysbuf on ks==0.
// ---------------------------------------------------------------------------
__device__ __forceinline__ void phase1_iter(char* smem, int ks, int cid,
                                            int buf, int tid, int lane, int wid) {
    const int i  = cid >> 3;
    const int j0 = (cid & 7) * TJ;
    const int j  = ks * 8 + wid;
    const int c  = lane * 4;
    float4 a = *(const float4*)(g_A + i * HID + c);
    float4 b = *(const float4*)(g_B + (j0 + j) * HID + c);
    float v0 = tanh_fast(a.x + b.x);
    float v1 = tanh_fast(a.y + b.y);
    float v2 = tanh_fast(a.z + b.z);
    float v3 = tanh_fast(a.w + b.w);
    uint32_t h0, l0, h1, l1;
    split2h(v0, v1, h0, l0);
    split2h(v2, v3, h1, l1);
    char* hb = smem + SM_H1 + buf * H1_BUF_B;
    uint32_t off = (uint32_t)(j * PITCH_B + lane * 8);
    *(uint2*)(hb + off) = make_uint2(h0, h1);
    *(uint2*)(hb + 17408 + off) = make_uint2(l0, l1);
    if (ks == 0 && tid < TJ)
        ((float*)(smem + SM_YS))[buf * TJ + tid] = g_y[j0 + tid];
}

// ---------------------------------------------------------------------------
// Main persistent kernel: software-pipelined tanh || fp16 mma.sync
// 256 threads = 8 warps. Warp grid 2(m) x 4(n): warp tile = 32 j x 32 k.
// ---------------------------------------------------------------------------
__global__ void __launch_bounds__(256, 2) modnet_mma_kernel(
        const float* __restrict__ W2,
        const float* __restrict__ b2,
        const float* __restrict__ W3) {
    extern __shared__ char smem[];
    const uint32_t sb = smem_u32(smem);
    const int tid = threadIdx.x, lane = tid & 31, wid = tid >> 5;
    const int wm = wid & 1, wn = wid >> 1;

    // ---- prologue: W2^T (fp16 hi only) into smem ----
    for (int e = tid; e < HID * 64; e += 256) {
        int n = e & 127, cp = e >> 7, c = cp * 2;
        __half2 h = __floats2half2_rn(W2[c * HID + n], W2[(c + 1) * HID + n]);
        *(uint32_t*)(smem + SM_W2HI + (uint32_t)(n * PITCH_B + cp * 4)) = h2u(h);
    }
    if (tid < HID) {
        float2 v; v.x = b2[tid]; v.y = W3[tid];
        *(float2*)(smem + SM_B2W3 + tid * 8) = v;
    }
    __syncthreads();

    // lane-invariant ldmatrix addressing (within an h1 buffer / W2)
    const uint32_t a_row  = (uint32_t)(wm * 32 + (lane & 15));
    const uint32_t a_coff = (uint32_t)((lane >> 4) * 16);
    const uint32_t aOff   = a_row * PITCH_B + a_coff;        // + buf base
    const uint32_t b_n    = (uint32_t)(wn * 32 + ((lane >> 4) << 3) + (lane & 7));
    const uint32_t b_coff = (uint32_t)(((lane >> 3) & 1) * 16);
    const uint32_t bHbase = sb + SM_W2HI + b_n * PITCH_B + b_coff;

    const float2* bw = (const float2*)(smem + SM_B2W3);
    float* red = (float*)(smem + SM_RED);
    const float* ys = (const float*)(smem + SM_YS);

    // phase 1 of the first chunk
    const int cid0 = blockIdx.x;
    if (cid0 < NCHUNK) {
        #pragma unroll
        for (int ks = 0; ks < 8; ks++)
            phase1_iter(smem, ks, cid0, 0, tid, lane, wid);
    }
    __syncthreads();

    int buf = 0;
    for (int cid = cid0; cid < NCHUNK; cid += NCTA) {
        const int next = cid + NCTA;
        const bool has_next = (next < NCHUNK);
        const uint32_t aHb = sb + SM_H1 + (uint32_t)(buf * H1_BUF_B) + aOff;
        const uint32_t aLb = aHb + 17408;

        // ---- fused: GEMM(cid) interleaved with phase1(next) ----
        float acc[2][4][4];
        #pragma unroll
        for (int mf = 0; mf < 2; mf++)
            #pragma unroll
            for (int nf = 0; nf < 4; nf++)
                #pragma unroll
                for (int q = 0; q < 4; q++) acc[mf][nf][q] = 0.0f;

        #pragma unroll 2
        for (int ks = 0; ks < 8; ks++) {
            const uint32_t kb = (uint32_t)(ks * 32);
            uint32_t ah[2][4], al[2][4], bh[4][2];
            #pragma unroll
            for (int mf = 0; mf < 2; mf++) {
                uint32_t off = (uint32_t)(mf * 16 * PITCH_B) + kb;
                ldsm4(ah[mf][0], ah[mf][1], ah[mf][2], ah[mf][3], aHb + off);
                ldsm4(al[mf][0], al[mf][1], al[mf][2], al[mf][3], aLb + off);
            }
            #pragma unroll
            for (int np = 0; np < 2; np++) {
                uint32_t off = (uint32_t)(np * 16 * PITCH_B) + kb;
                ldsm4(bh[np*2][0], bh[np*2][1], bh[np*2+1][0], bh[np*2+1][1],
                      bHbase + off);
            }
            #pragma unroll
            for (int mf = 0; mf < 2; mf++)
                #pragma unroll
                for (int nf = 0; nf < 4; nf++) {
                    mma_f16(acc[mf][nf], ah[mf], bh[nf]);
                    mma_f16(acc[mf][nf], al[mf], bh[nf]);
                }
            // interleaved: 1/8 of next chunk's tanh tile (MUFU/FP under HMMA)
            if (has_next)
                phase1_iter(smem, ks, next, buf ^ 1, tid, lane, wid);
        }

        // ---- fused epilogue from registers ----
        const int r = lane >> 2, q2 = (lane & 3) * 2;
        const float* yb = ys + buf * TJ;
        float s = 0.0f;
        #pragma unroll
        for (int mf = 0; mf < 2; mf++) {
            const int jr = wm * 32 + mf * 16 + r;
            const float y0 = yb[jr];
            const float y1 = yb[jr + 8];
            #pragma unroll
            for (int nf = 0; nf < 4; nf++) {
                const int k = wn * 32 + nf * 8 + q2;
                float2 c0 = bw[k], c1 = bw[k + 1];
                s += y0 * (tanh_fast(acc[mf][nf][0] + c0.x) * c0.y
                         + tanh_fast(acc[mf][nf][1] + c1.x) * c1.y)
                   + y1 * (tanh_fast(acc[mf][nf][2] + c0.x) * c0.y
                         + tanh_fast(acc[mf][nf][3] + c1.x) * c1.y);
            }
        }
        #pragma unroll
        for (int o = 16; o > 0; o >>= 1) s += __shfl_xor_sync(0xffffffffu, s, o);
        if (lane == 0) red[wid] = s;
        __syncthreads();
        if (tid == 0) {
            float t = 0.0f;
            #pragma unroll
            for (int w = 0; w < 8; w++) t += red[w];     // fixed order
            g_part[cid] = t;
        }
        __syncthreads();    // red consumed; buffers safe for next iteration
        buf ^= 1;
    }
}

// ---------------------------------------------------------------------------
__global__ void finalize_kernel(const float* __restrict__ b3,
                                float* __restrict__ out) {
    int i = blockIdx.x * blockDim.x + threadIdx.x;
    if (i < N_PTS) {
        float s = b3[0] * g_Y;
        #pragma unroll
        for (int t = 0; t < JT; t++) s += g_part[i * JT + t];
        out[i] = s;
    }
}

// ---------------------------------------------------------------------------
extern "C" void kernel_launch(void* const* d_in, const int* in_sizes, int n_in,
                              void* d_out, int out_size) {
    const float* inp = (const float*)d_in[0];   // [2048, 2]
    const float* qx  = (const float*)d_in[1];   // [512, 2]
    const float* ep  = (const float*)d_in[2];   // [1]
    const float* W1  = (const float*)d_in[3];   // [4, 128]
    const float* b1  = (const float*)d_in[4];   // [128]
    const float* W2  = (const float*)d_in[5];   // [128, 128]
    const float* b2  = (const float*)d_in[6];   // [128]
    const float* W3  = (const float*)d_in[7];   // [128, 1]
    const float* b3  = (const float*)d_in[8];   // [1]
    float* out = (float*)d_out;                 // [2048, 1]
    (void)in_sizes; (void)n_in; (void)out_size;

    cudaFuncSetAttribute(modnet_mma_kernel,
                         cudaFuncAttributeMaxDynamicSharedMemorySize, SMEM_TOTAL);

    prep_ab_kernel<<<(N_PTS * 32 + M_PTS * 32 + 255) / 256, 256>>>(inp, qx, W1, b1);
    prep_y_kernel<<<1, 512>>>(qx, ep);
    modnet_mma_kernel<<<NCTA, 256, SMEM_TOTAL>>>(W2, b2, W3);
    finalize_kernel<<<(N_PTS + 255) / 256, 256>>>(b3, out);
}

// round 7
// speedup vs baseline: 1.0740x; 1.0740x over previous
#include <cuda_runtime.h>
#include <cuda_fp16.h>
#include <stdint.h>
#include <string.h>

#define N_PTS 2048
#define M_PTS 512
#define HID   128
#define TJ    64                  // j's per chunk
#define JT    (M_PTS / TJ)        // 8 chunks per i
#define NCHUNK (N_PTS * JT)       // 16384
#define NCTA  296                 // 2 per SM
#define PI_F  3.14159265358979323846f
#define SCALE_2LOG2E 2.885390081777926815f   // 2*log2(e)

// smem pitch: 136 fp16 per row = 272 B = 17 x 16B -> ldmatrix conflict-free
#define PITCH_B 272

// ---- shared memory layout (bytes) ----
#define SM_W2HI  0                      // [128][136] fp16 (W2^T*S hi) 34816 B
#define SM_H1HI  34816                  // [64][136] fp16  17408 B
#define SM_H1LO  52224                  // 17408 B
#define SM_B2W3  69632                  // 128 x float2 (b2*S, W3)
#define SM_YS    70656                  // 64 floats (y prefetch)
#define SM_RED   70912                  // 8 floats
#define SMEM_TOTAL 71040

// ---- device scratch ----
__device__ __align__(16) float g_A[N_PTS * HID];   // pre-scaled by 2*log2e
__device__ __align__(16) float g_B[M_PTS * HID];   // pre-scaled by 2*log2e
__device__ __align__(16) float g_y[M_PTS];
__device__ float g_Y;
__device__ __align__(16) float g_part[NCHUNK];

// ---------------------------------------------------------------------------
// tanh from pre-scaled argument: arg = 2*log2e*x.  t = 1 - 2*rcp(ex2(arg)+1)
__device__ __forceinline__ float tanh_scaled(float arg) {
    float e;
    asm("ex2.approx.f32 %0, %1;" : "=f"(e) : "f"(arg));
    float r;
    asm("rcp.approx.f32 %0, %1;" : "=f"(r) : "f"(e + 1.0f));
    return fmaf(-2.0f, r, 1.0f);
}

__device__ __forceinline__ uint32_t smem_u32(const void* p) {
    uint32_t a;
    asm("{ .reg .u64 t; cvta.to.shared.u64 t, %1; cvt.u32.u64 %0, t; }"
        : "=r"(a) : "l"(p));
    return a;
}

__device__ __forceinline__ void ldsm4(uint32_t& r0, uint32_t& r1,
                                      uint32_t& r2, uint32_t& r3, uint32_t addr) {
    asm volatile("ldmatrix.sync.aligned.m8n8.x4.shared.b16 {%0,%1,%2,%3}, [%4];"
                 : "=r"(r0), "=r"(r1), "=r"(r2), "=r"(r3) : "r"(addr));
}

__device__ __forceinline__ void mma_f16(float* d, const uint32_t* a,
                                        const uint32_t* b) {
    asm volatile(
        "mma.sync.aligned.m16n8k16.row.col.f32.f16.f16.f32 "
        "{%0,%1,%2,%3}, {%4,%5,%6,%7}, {%8,%9}, {%0,%1,%2,%3};"
        : "+f"(d[0]), "+f"(d[1]), "+f"(d[2]), "+f"(d[3])
        : "r"(a[0]), "r"(a[1]), "r"(a[2]), "r"(a[3]), "r"(b[0]), "r"(b[1]));
}

__device__ __forceinline__ uint32_t h2u(__half2 h) {
    uint32_t u; memcpy(&u, &h, 4); return u;
}

// fp32 pair -> packed fp16 hi + packed fp16 lo (residual)
__device__ __forceinline__ void split2h(float v0, float v1,
                                        uint32_t& hi, uint32_t& lo) {
    __half2 h = __floats2half2_rn(v0, v1);
    float2 hf = __half22float2(h);
    __half2 l = __floats2half2_rn(v0 - hf.x, v1 - hf.y);
    hi = h2u(h); lo = h2u(l);
}

// ---------------------------------------------------------------------------
// Precompute A,B (layer-1 factorization), pre-scaled by 2*log2e for ex2.
// ---------------------------------------------------------------------------
__global__ void prep_ab_kernel(const float* __restrict__ inp,
                               const float* __restrict__ qx,
                               const float* __restrict__ W1,
                               const float* __restrict__ b1) {
    int idx = blockIdx.x * blockDim.x + threadIdx.x;
    const float4* W14 = (const float4*)W1;
    const float S = SCALE_2LOG2E;
    if (idx < N_PTS * 32) {
        int n = idx >> 5, v = idx & 31;
        float x0 = inp[2 * n] * S, x1 = inp[2 * n + 1] * S;
        float4 wa = W14[v], wb = W14[32 + v];
        float4 r;
        r.x = x0 * wa.x + x1 * wb.x;
        r.y = x0 * wa.y + x1 * wb.y;
        r.z = x0 * wa.z + x1 * wb.z;
        r.w = x0 * wa.w + x1 * wb.w;
        ((float4*)g_A)[idx] = r;
    } else {
        int t = idx - N_PTS * 32;
        if (t < M_PTS * 32) {
            int m = t >> 5, v = t & 31;
            float q0 = qx[2 * m] * S, q1 = qx[2 * m + 1] * S;
            float4 wc = W14[64 + v], wd = W14[96 + v];
            float4 bb = ((const float4*)b1)[v];
            float4 r;
            r.x = q0 * wc.x + q1 * wd.x + bb.x * S;
            r.y = q0 * wc.y + q1 * wd.y + bb.y * S;
            r.z = q0 * wc.z + q1 * wd.z + bb.z * S;
            r.w = q0 * wc.w + q1 * wd.w + bb.w * S;
            ((float4*)g_B)[t] = r;
        }
    }
}

__global__ void prep_y_kernel(const float* __restrict__ qx,
                              const float* __restrict__ ep) {
    __shared__ float red[512];
    int j = threadIdx.x;
    float e = ep[0];
    float y = sinf(PI_F * e * qx[2 * j]) * sinf(PI_F * e * qx[2 * j + 1]);
    g_y[j] = y;
    red[j] = y;
    __syncthreads();
    for (int s = 256; s > 0; s >>= 1) {
        if (j < s) red[j] += red[j + s];
        __syncthreads();
    }
    if (j == 0) g_Y = red[0];
}

// ---------------------------------------------------------------------------
// Main persistent kernel. 256 threads = 8 warps.
// Phase 1: thread owns c=lane*4 (A row hoisted); warp w fills j rows w,8+w,...
// GEMM: warp grid 2(m) x 4(n): warp tile = 32 j x 32 k, 2-pass fp16.
// ---------------------------------------------------------------------------
__global__ void __launch_bounds__(256, 2) modnet_mma_kernel(
        const float* __restrict__ W2,
        const float* __restrict__ b2,
        const float* __restrict__ W3) {
    extern __shared__ char smem[];
    const uint32_t sb = smem_u32(smem);
    const int tid = threadIdx.x, lane = tid & 31, wid = tid >> 5;
    const int wm = wid & 1, wn = wid >> 1;

    // ---- prologue: W2^T * 2log2e (fp16 hi) into smem ----
    for (int e = tid; e < HID * 64; e += 256) {
        int n = e & 127, cp = e >> 7, c = cp * 2;
        __half2 h = __floats2half2_rn(W2[c * HID + n] * SCALE_2LOG2E,
                                      W2[(c + 1) * HID + n] * SCALE_2LOG2E);
        *(uint32_t*)(smem + SM_W2HI + (uint32_t)(n * PITCH_B + cp * 4)) = h2u(h);
    }
    if (tid < HID) {
        float2 v; v.x = b2[tid] * SCALE_2LOG2E; v.y = W3[tid];
        *(float2*)(smem + SM_B2W3 + tid * 8) = v;
    }
    __syncthreads();

    // lane-invariant ldmatrix addressing
    const uint32_t a_row  = (uint32_t)(wm * 32 + (lane & 15));
    const uint32_t a_coff = (uint32_t)((lane >> 4) * 16);
    const uint32_t aHbase = sb + SM_H1HI + a_row * PITCH_B + a_coff;
    const uint32_t aLbase = sb + SM_H1LO + a_row * PITCH_B + a_coff;
    const uint32_t b_n    = (uint32_t)(wn * 32 + ((lane >> 4) << 3) + (lane & 7));
    const uint32_t b_coff = (uint32_t)(((lane >> 3) & 1) * 16);
    const uint32_t bHbase = sb + SM_W2HI + b_n * PITCH_B + b_coff;

    const float2* bw = (const float2*)(smem + SM_B2W3);
    float* red = (float*)(smem + SM_RED);
    const float* ys = (const float*)(smem + SM_YS);

    const int c4 = lane * 4;                 // this thread's column slice
    const uint32_t h1off0 = (uint32_t)(wid * PITCH_B + lane * 8);

    for (int cid = blockIdx.x; cid < NCHUNK; cid += NCTA) {
        const int i  = cid >> 3;
        const int j0 = (cid & 7) * TJ;

        // ---- phase 1: h1 = tanh(A_i + B_j) -> fp16 hi/lo ----
        const float4 a = *(const float4*)(g_A + i * HID + c4);   // hoisted
        #pragma unroll
        for (int it = 0; it < 8; it++) {
            const int j = it * 8 + wid;
            float4 b = *(const float4*)(g_B + (j0 + j) * HID + c4);
            float v0 = tanh_scaled(a.x + b.x);
            float v1 = tanh_scaled(a.y + b.y);
            float v2 = tanh_scaled(a.z + b.z);
            float v3 = tanh_scaled(a.w + b.w);
            uint32_t h0, l0, h1, l1;
            split2h(v0, v1, h0, l0);
            split2h(v2, v3, h1, l1);
            uint32_t off = h1off0 + (uint32_t)(it * 8 * PITCH_B);
            *(uint2*)(smem + SM_H1HI + off) = make_uint2(h0, h1);
            *(uint2*)(smem + SM_H1LO + off) = make_uint2(l0, l1);
        }
        if (tid < TJ) ((float*)(smem + SM_YS))[tid] = g_y[j0 + tid];
        __syncthreads();

        // ---- phase 2: GEMM, warp tile 32x32, K=128, 2 fp16 passes ----
        float acc[2][4][4];
        #pragma unroll
        for (int mf = 0; mf < 2; mf++)
            #pragma unroll
            for (int nf = 0; nf < 4; nf++)
                #pragma unroll
                for (int q = 0; q < 4; q++) acc[mf][nf][q] = 0.0f;

        #pragma unroll 2
        for (int ks = 0; ks < 8; ks++) {
            const uint32_t kb = (uint32_t)(ks * 32);
            uint32_t ah[2][4], al[2][4], bh[4][2];
            #pragma unroll
            for (int mf = 0; mf < 2; mf++) {
                uint32_t off = (uint32_t)(mf * 16 * PITCH_B) + kb;
                ldsm4(ah[mf][0], ah[mf][1], ah[mf][2], ah[mf][3], aHbase + off);
                ldsm4(al[mf][0], al[mf][1], al[mf][2], al[mf][3], aLbase + off);
            }
            #pragma unroll
            for (int np = 0; np < 2; np++) {
                uint32_t off = (uint32_t)(np * 16 * PITCH_B) + kb;
                ldsm4(bh[np*2][0], bh[np*2][1], bh[np*2+1][0], bh[np*2+1][1],
                      bHbase + off);
            }
            #pragma unroll
            for (int mf = 0; mf < 2; mf++)
                #pragma unroll
                for (int nf = 0; nf < 4; nf++) {
                    mma_f16(acc[mf][nf], ah[mf], bh[nf]);
                    mma_f16(acc[mf][nf], al[mf], bh[nf]);
                }
        }

        // ---- phase 3: fused epilogue (acc already scaled by 2log2e) ----
        const int r = lane >> 2, q2 = (lane & 3) * 2;
        float s = 0.0f;
        #pragma unroll
        for (int mf = 0; mf < 2; mf++) {
            const int jr = wm * 32 + mf * 16 + r;
            const float y0 = ys[jr];
            const float y1 = ys[jr + 8];
            #pragma unroll
            for (int nf = 0; nf < 4; nf++) {
                const int k = wn * 32 + nf * 8 + q2;
                float2 c0 = bw[k], c1 = bw[k + 1];
                s += y0 * (tanh_scaled(acc[mf][nf][0] + c0.x) * c0.y
                         + tanh_scaled(acc[mf][nf][1] + c1.x) * c1.y)
                   + y1 * (tanh_scaled(acc[mf][nf][2] + c0.x) * c0.y
                         + tanh_scaled(acc[mf][nf][3] + c1.x) * c1.y);
            }
        }
        #pragma unroll
        for (int o = 16; o > 0; o >>= 1) s += __shfl_xor_sync(0xffffffffu, s, o);
        if (lane == 0) red[wid] = s;
        __syncthreads();
        if (tid == 0) {
            float t = 0.0f;
            #pragma unroll
            for (int w = 0; w < 8; w++) t += red[w];     // fixed order
            g_part[cid] = t;
        }
        __syncthreads();    // red + ys consumed; buffers safe next iteration
    }
}

// ---------------------------------------------------------------------------
__global__ void finalize_kernel(const float* __restrict__ b3,
                                float* __restrict__ out) {
    int i = blockIdx.x * blockDim.x + threadIdx.x;
    if (i < N_PTS) {
        float s = b3[0] * g_Y;
        #pragma unroll
        for (int t = 0; t < JT; t++) s += g_part[i * JT + t];
        out[i] = s;
    }
}

// ---------------------------------------------------------------------------
extern "C" void kernel_launch(void* const* d_in, const int* in_sizes, int n_in,
                              void* d_out, int out_size) {
    const float* inp = (const float*)d_in[0];   // [2048, 2]
    const float* qx  = (const float*)d_in[1];   // [512, 2]
    const float* ep  = (const float*)d_in[2];   // [1]
    const float* W1  = (const float*)d_in[3];   // [4, 128]
    const float* b1  = (const float*)d_in[4];   // [128]
    const float* W2  = (const float*)d_in[5];   // [128, 128]
    const float* b2  = (const float*)d_in[6];   // [128]
    const float* W3  = (const float*)d_in[7];   // [128, 1]
    const float* b3  = (const float*)d_in[8];   // [1]
    float* out = (float*)d_out;                 // [2048, 1]
    (void)in_sizes; (void)n_in; (void)out_size;

    cudaFuncSetAttribute(modnet_mma_kernel,
                         cudaFuncAttributeMaxDynamicSharedMemorySize, SMEM_TOTAL);

    prep_ab_kernel<<<(N_PTS * 32 + M_PTS * 32 + 255) / 256, 256>>>(inp, qx, W1, b1);
    prep_y_kernel<<<1, 512>>>(qx, ep);
    modnet_mma_kernel<<<NCTA, 256, SMEM_TOTAL>>>(W2, b2, W3);
    finalize_kernel<<<(N_PTS + 255) / 256, 256>>>(b3, out);
}

// round 8
// speedup vs baseline: 1.1462x; 1.0672x over previous
#include <cuda_runtime.h>
#include <cuda_fp16.h>
#include <stdint.h>
#include <string.h>

#define N_PTS 2048
#define M_PTS 512
#define HID   128
#define TJ    64                  // j's per chunk
#define JT    (M_PTS / TJ)        // 8 chunks per i
#define NCHUNK (N_PTS * JT)       // 16384
#define NCTA  444                 // 3 per SM
#define PI_F  3.14159265358979323846f
#define SCALE_2LOG2E 2.885390081777926815f   // 2*log2(e)

// smem pitch: 136 fp16 per row = 272 B = 17 x 16B -> ldmatrix conflict-free
#define PITCH_B 272

// ---- shared memory layout (bytes) ----
#define SM_W2HI  0                      // [128][136] fp16 (W2^T*S hi) 34816 B
#define SM_H1HI  34816                  // [64][136] fp16  17408 B
#define SM_H1LO  52224                  // 17408 B
#define SM_B2W3  69632                  // 128 x float2 (b2*S, W3)
#define SM_YS    70656                  // 64 floats (y prefetch)
#define SM_RED   70912                  // 8 floats + is_last flag
#define SMEM_TOTAL 71040

// ---- device scratch ----
__device__ __align__(16) float g_A[N_PTS * HID];   // pre-scaled by 2*log2e
__device__ __align__(16) float g_B[M_PTS * HID];   // pre-scaled by 2*log2e
__device__ __align__(16) float g_y[M_PTS];
__device__ float g_Y;
__device__ __align__(16) float g_part[NCHUNK];
__device__ unsigned int g_done;                    // zero-init; reset each run

// ---------------------------------------------------------------------------
// tanh from pre-scaled argument: arg = 2*log2e*x.  t = 1 - 2*rcp(ex2(arg)+1)
__device__ __forceinline__ float tanh_scaled(float arg) {
    float e;
    asm("ex2.approx.f32 %0, %1;" : "=f"(e) : "f"(arg));
    float r;
    asm("rcp.approx.f32 %0, %1;" : "=f"(r) : "f"(e + 1.0f));
    return fmaf(-2.0f, r, 1.0f);
}

__device__ __forceinline__ uint32_t smem_u32(const void* p) {
    uint32_t a;
    asm("{ .reg .u64 t; cvta.to.shared.u64 t, %1; cvt.u32.u64 %0, t; }"
        : "=r"(a) : "l"(p));
    return a;
}

__device__ __forceinline__ void ldsm4(uint32_t& r0, uint32_t& r1,
                                      uint32_t& r2, uint32_t& r3, uint32_t addr) {
    asm volatile("ldmatrix.sync.aligned.m8n8.x4.shared.b16 {%0,%1,%2,%3}, [%4];"
                 : "=r"(r0), "=r"(r1), "=r"(r2), "=r"(r3) : "r"(addr));
}

__device__ __forceinline__ void mma_f16(float* d, const uint32_t* a,
                                        const uint32_t* b) {
    asm volatile(
        "mma.sync.aligned.m16n8k16.row.col.f32.f16.f16.f32 "
        "{%0,%1,%2,%3}, {%4,%5,%6,%7}, {%8,%9}, {%0,%1,%2,%3};"
        : "+f"(d[0]), "+f"(d[1]), "+f"(d[2]), "+f"(d[3])
        : "r"(a[0]), "r"(a[1]), "r"(a[2]), "r"(a[3]), "r"(b[0]), "r"(b[1]));
}

__device__ __forceinline__ uint32_t h2u(__half2 h) {
    uint32_t u; memcpy(&u, &h, 4); return u;
}

// fp32 pair -> packed fp16 hi + packed fp16 lo (residual)
__device__ __forceinline__ void split2h(float v0, float v1,
                                        uint32_t& hi, uint32_t& lo) {
    __half2 h = __floats2half2_rn(v0, v1);
    float2 hf = __half22float2(h);
    __half2 l = __floats2half2_rn(v0 - hf.x, v1 - hf.y);
    hi = h2u(h); lo = h2u(l);
}

// ---------------------------------------------------------------------------
// Precompute A,B (layer-1 factorization), pre-scaled by 2*log2e for ex2.
// ---------------------------------------------------------------------------
__global__ void prep_ab_kernel(const float* __restrict__ inp,
                               const float* __restrict__ qx,
                               const float* __restrict__ W1,
                               const float* __restrict__ b1) {
    int idx = blockIdx.x * blockDim.x + threadIdx.x;
    const float4* W14 = (const float4*)W1;
    const float S = SCALE_2LOG2E;
    if (idx < N_PTS * 32) {
        int n = idx >> 5, v = idx & 31;
        float x0 = inp[2 * n] * S, x1 = inp[2 * n + 1] * S;
        float4 wa = W14[v], wb = W14[32 + v];
        float4 r;
        r.x = x0 * wa.x + x1 * wb.x;
        r.y = x0 * wa.y + x1 * wb.y;
        r.z = x0 * wa.z + x1 * wb.z;
        r.w = x0 * wa.w + x1 * wb.w;
        ((float4*)g_A)[idx] = r;
    } else {
        int t = idx - N_PTS * 32;
        if (t < M_PTS * 32) {
            int m = t >> 5, v = t & 31;
            float q0 = qx[2 * m] * S, q1 = qx[2 * m + 1] * S;
            float4 wc = W14[64 + v], wd = W14[96 + v];
            float4 bb = ((const float4*)b1)[v];
            float4 r;
            r.x = q0 * wc.x + q1 * wd.x + bb.x * S;
            r.y = q0 * wc.y + q1 * wd.y + bb.y * S;
            r.z = q0 * wc.z + q1 * wd.z + bb.z * S;
            r.w = q0 * wc.w + q1 * wd.w + bb.w * S;
            ((float4*)g_B)[t] = r;
        }
    }
}

__global__ void prep_y_kernel(const float* __restrict__ qx,
                              const float* __restrict__ ep) {
    __shared__ float red[512];
    int j = threadIdx.x;
    float e = ep[0];
    float y = sinf(PI_F * e * qx[2 * j]) * sinf(PI_F * e * qx[2 * j + 1]);
    g_y[j] = y;
    red[j] = y;
    __syncthreads();
    for (int s = 256; s > 0; s >>= 1) {
        if (j < s) red[j] += red[j + s];
        __syncthreads();
    }
    if (j == 0) g_Y = red[0];
}

// ---------------------------------------------------------------------------
// Main persistent kernel. 256 threads = 8 warps, 3 CTAs/SM.
// Phase 1: thread owns c=lane*4 (A row hoisted); warp w fills j rows w,8+w,...
// GEMM: warp grid 2(m) x 4(n): warp tile = 32 j x 32 k, 2-pass fp16.
// Tail: last CTA (atomic ticket) sums g_part -> out (deterministic order).
// ---------------------------------------------------------------------------
__global__ void __launch_bounds__(256, 3) modnet_mma_kernel(
        const float* __restrict__ W2,
        const float* __restrict__ b2,
        const float* __restrict__ W3,
        const float* __restrict__ b3,
        float* __restrict__ out) {
    extern __shared__ char smem[];
    const uint32_t sb = smem_u32(smem);
    const int tid = threadIdx.x, lane = tid & 31, wid = tid >> 5;
    const int wm = wid & 1, wn = wid >> 1;

    // ---- prologue: W2^T * 2log2e (fp16 hi) into smem ----
    for (int e = tid; e < HID * 64; e += 256) {
        int n = e & 127, cp = e >> 7, c = cp * 2;
        __half2 h = __floats2half2_rn(W2[c * HID + n] * SCALE_2LOG2E,
                                      W2[(c + 1) * HID + n] * SCALE_2LOG2E);
        *(uint32_t*)(smem + SM_W2HI + (uint32_t)(n * PITCH_B + cp * 4)) = h2u(h);
    }
    if (tid < HID) {
        float2 v; v.x = b2[tid] * SCALE_2LOG2E; v.y = W3[tid];
        *(float2*)(smem + SM_B2W3 + tid * 8) = v;
    }
    __syncthreads();

    // lane-invariant ldmatrix addressing
    const uint32_t a_row  = (uint32_t)(wm * 32 + (lane & 15));
    const uint32_t a_coff = (uint32_t)((lane >> 4) * 16);
    const uint32_t aHbase = sb + SM_H1HI + a_row * PITCH_B + a_coff;
    const uint32_t aLbase = sb + SM_H1LO + a_row * PITCH_B + a_coff;
    const uint32_t b_n    = (uint32_t)(wn * 32 + ((lane >> 4) << 3) + (lane & 7));
    const uint32_t b_coff = (uint32_t)(((lane >> 3) & 1) * 16);
    const uint32_t bHbase = sb + SM_W2HI + b_n * PITCH_B + b_coff;

    const float2* bw = (const float2*)(smem + SM_B2W3);
    float* red = (float*)(smem + SM_RED);
    const float* ys = (const float*)(smem + SM_YS);

    const int c4 = lane * 4;                 // this thread's column slice
    const uint32_t h1off0 = (uint32_t)(wid * PITCH_B + lane * 8);

    for (int cid = blockIdx.x; cid < NCHUNK; cid += NCTA) {
        const int i  = cid / JT;
        const int j0 = (cid % JT) * TJ;

        // ---- phase 1: h1 = tanh(A_i + B_j) -> fp16 hi/lo ----
        const float4 a = *(const float4*)(g_A + i * HID + c4);   // hoisted
        #pragma unroll
        for (int it = 0; it < 8; it++) {
            const int j = it * 8 + wid;
            float4 b = *(const float4*)(g_B + (j0 + j) * HID + c4);
            float v0 = tanh_scaled(a.x + b.x);
            float v1 = tanh_scaled(a.y + b.y);
            float v2 = tanh_scaled(a.z + b.z);
            float v3 = tanh_scaled(a.w + b.w);
            uint32_t h0, l0, h1, l1;
            split2h(v0, v1, h0, l0);
            split2h(v2, v3, h1, l1);
            uint32_t off = h1off0 + (uint32_t)(it * 8 * PITCH_B);
            *(uint2*)(smem + SM_H1HI + off) = make_uint2(h0, h1);
            *(uint2*)(smem + SM_H1LO + off) = make_uint2(l0, l1);
        }
        if (tid < TJ) ((float*)(smem + SM_YS))[tid] = g_y[j0 + tid];
        __syncthreads();

        // ---- phase 2: GEMM, warp tile 32x32, K=128, 2 fp16 passes ----
        float acc[2][4][4];
        #pragma unroll
        for (int mf = 0; mf < 2; mf++)
            #pragma unroll
            for (int nf = 0; nf < 4; nf++)
                #pragma unroll
                for (int q = 0; q < 4; q++) acc[mf][nf][q] = 0.0f;

        #pragma unroll 2
        for (int ks = 0; ks < 8; ks++) {
            const uint32_t kb = (uint32_t)(ks * 32);
            uint32_t ah[2][4], al[2][4], bh[4][2];
            #pragma unroll
            for (int mf = 0; mf < 2; mf++) {
                uint32_t off = (uint32_t)(mf * 16 * PITCH_B) + kb;
                ldsm4(ah[mf][0], ah[mf][1], ah[mf][2], ah[mf][3], aHbase + off);
                ldsm4(al[mf][0], al[mf][1], al[mf][2], al[mf][3], aLbase + off);
            }
            #pragma unroll
            for (int np = 0; np < 2; np++) {
                uint32_t off = (uint32_t)(np * 16 * PITCH_B) + kb;
                ldsm4(bh[np*2][0], bh[np*2][1], bh[np*2+1][0], bh[np*2+1][1],
                      bHbase + off);
            }
            #pragma unroll
            for (int mf = 0; mf < 2; mf++)
                #pragma unroll
                for (int nf = 0; nf < 4; nf++) {
                    mma_f16(acc[mf][nf], ah[mf], bh[nf]);
                    mma_f16(acc[mf][nf], al[mf], bh[nf]);
                }
        }

        // ---- phase 3: fused epilogue (acc already scaled by 2log2e) ----
        const int r = lane >> 2, q2 = (lane & 3) * 2;
        float s = 0.0f;
        #pragma unroll
        for (int mf = 0; mf < 2; mf++) {
            const int jr = wm * 32 + mf * 16 + r;
            const float y0 = ys[jr];
            const float y1 = ys[jr + 8];
            #pragma unroll
            for (int nf = 0; nf < 4; nf++) {
                const int k = wn * 32 + nf * 8 + q2;
                float2 c0 = bw[k], c1 = bw[k + 1];
                s += y0 * (tanh_scaled(acc[mf][nf][0] + c0.x) * c0.y
                         + tanh_scaled(acc[mf][nf][1] + c1.x) * c1.y)
                   + y1 * (tanh_scaled(acc[mf][nf][2] + c0.x) * c0.y
                         + tanh_scaled(acc[mf][nf][3] + c1.x) * c1.y);
            }
        }
        #pragma unroll
        for (int o = 16; o > 0; o >>= 1) s += __shfl_xor_sync(0xffffffffu, s, o);
        if (lane == 0) red[wid] = s;
        __syncthreads();
        if (tid == 0) {
            float t = 0.0f;
            #pragma unroll
            for (int w = 0; w < 8; w++) t += red[w];     // fixed order
            g_part[cid] = t;
        }
        __syncthreads();    // red + ys consumed; buffers safe next iteration
    }

    // ---- finalize tail: last CTA to arrive sums g_part -> out ----
    unsigned int* is_last = (unsigned int*)(smem + SM_RED + 32);
    __threadfence();                      // publish g_part before ticket
    __syncthreads();
    if (tid == 0)
        *is_last = (atomicAdd(&g_done, 1u) == (unsigned)(NCTA - 1)) ? 1u : 0u;
    __syncthreads();
    if (*is_last) {
        const float base = b3[0] * g_Y;
        for (int i = tid; i < N_PTS; i += 256) {
            float s2 = base;
            #pragma unroll
            for (int t = 0; t < JT; t++) s2 += g_part[i * JT + t];
            out[i] = s2;
        }
        if (tid == 0) g_done = 0;         // reset: deterministic graph replays
    }
}

// ---------------------------------------------------------------------------
extern "C" void kernel_launch(void* const* d_in, const int* in_sizes, int n_in,
                              void* d_out, int out_size) {
    const float* inp = (const float*)d_in[0];   // [2048, 2]
    const float* qx  = (const float*)d_in[1];   // [512, 2]
    const float* ep  = (const float*)d_in[2];   // [1]
    const float* W1  = (const float*)d_in[3];   // [4, 128]
    const float* b1  = (const float*)d_in[4];   // [128]
    const float* W2  = (const float*)d_in[5];   // [128, 128]
    const float* b2  = (const float*)d_in[6];   // [128]
    const float* W3  = (const float*)d_in[7];   // [128, 1]
    const float* b3  = (const float*)d_in[8];   // [1]
    float* out = (float*)d_out;                 // [2048, 1]
    (void)in_sizes; (void)n_in; (void)out_size;

    cudaFuncSetAttribute(modnet_mma_kernel,
                         cudaFuncAttributeMaxDynamicSharedMemorySize, SMEM_TOTAL);

    prep_ab_kernel<<<(N_PTS * 32 + M_PTS * 32 + 255) / 256, 256>>>(inp, qx, W1, b1);
    prep_y_kernel<<<1, 512>>>(qx, ep);
    modnet_mma_kernel<<<NCTA, 256, SMEM_TOTAL>>>(W2, b2, W3, b3, out);
}

// round 9
// speedup vs baseline: 1.4394x; 1.2558x over previous
#include <cuda_runtime.h>
#include <cuda_fp16.h>
#include <stdint.h>
#include <string.h>

#define N_PTS 2048
#define M_PTS 512
#define HID   128
#define TJ    64                  // j's per chunk
#define JT    (M_PTS / TJ)        // 8 chunks per i
#define NCHUNK (N_PTS * JT)       // 16384
#define NCTA  444                 // 3 per SM
#define PI_F  3.14159265358979323846f
#define SCALE_2LOG2E 2.885390081777926815f   // 2*log2(e)

// smem pitch: 136 fp16 per row = 272 B = 17 x 16B -> ldmatrix conflict-free
#define PITCH_B 272

// ---- shared memory layout (bytes) ----
#define SM_W2HI  0                      // [128][136] fp16 (W2^T*S) 34816 B
#define SM_H1HI  34816                  // [64][136] fp16  17408 B
#define SM_B2W3  52224                  // 128 x float2 (b2*S, W3)
#define SM_YS    53248                  // 64 floats (y prefetch)
#define SM_RED   53504                  // 8 floats + is_last flag
#define SMEM_TOTAL 53632

// ---- device scratch ----
__device__ __align__(16) float g_A[N_PTS * HID];   // pre-scaled by 2*log2e
__device__ __align__(16) float g_B[M_PTS * HID];   // pre-scaled by 2*log2e
__device__ __align__(16) float g_y[M_PTS];
__device__ float g_Y;
__device__ __align__(16) float g_part[NCHUNK];
__device__ unsigned int g_done;                    // zero-init; reset each run

// ---------------------------------------------------------------------------
// tanh from pre-scaled argument: arg = 2*log2e*x.  t = 1 - 2*rcp(ex2(arg)+1)
__device__ __forceinline__ float tanh_scaled(float arg) {
    float e;
    asm("ex2.approx.f32 %0, %1;" : "=f"(e) : "f"(arg));
    float r;
    asm("rcp.approx.f32 %0, %1;" : "=f"(r) : "f"(e + 1.0f));
    return fmaf(-2.0f, r, 1.0f);
}

__device__ __forceinline__ uint32_t smem_u32(const void* p) {
    uint32_t a;
    asm("{ .reg .u64 t; cvta.to.shared.u64 t, %1; cvt.u32.u64 %0, t; }"
        : "=r"(a) : "l"(p));
    return a;
}

__device__ __forceinline__ void ldsm4(uint32_t& r0, uint32_t& r1,
                                      uint32_t& r2, uint32_t& r3, uint32_t addr) {
    asm volatile("ldmatrix.sync.aligned.m8n8.x4.shared.b16 {%0,%1,%2,%3}, [%4];"
                 : "=r"(r0), "=r"(r1), "=r"(r2), "=r"(r3) : "r"(addr));
}

__device__ __forceinline__ void mma_f16(float* d, const uint32_t* a,
                                        const uint32_t* b) {
    asm volatile(
        "mma.sync.aligned.m16n8k16.row.col.f32.f16.f16.f32 "
        "{%0,%1,%2,%3}, {%4,%5,%6,%7}, {%8,%9}, {%0,%1,%2,%3};"
        : "+f"(d[0]), "+f"(d[1]), "+f"(d[2]), "+f"(d[3])
        : "r"(a[0]), "r"(a[1]), "r"(a[2]), "r"(a[3]), "r"(b[0]), "r"(b[1]));
}

__device__ __forceinline__ uint32_t h2u(__half2 h) {
    uint32_t u; memcpy(&u, &h, 4); return u;
}

// ---------------------------------------------------------------------------
// Precompute A,B (layer-1 factorization), pre-scaled by 2*log2e for ex2.
// ---------------------------------------------------------------------------
__global__ void prep_ab_kernel(const float* __restrict__ inp,
                               const float* __restrict__ qx,
                               const float* __restrict__ W1,
                               const float* __restrict__ b1) {
    int idx = blockIdx.x * blockDim.x + threadIdx.x;
    const float4* W14 = (const float4*)W1;
    const float S = SCALE_2LOG2E;
    if (idx < N_PTS * 32) {
        int n = idx >> 5, v = idx & 31;
        float x0 = inp[2 * n] * S, x1 = inp[2 * n + 1] * S;
        float4 wa = W14[v], wb = W14[32 + v];
        float4 r;
        r.x = x0 * wa.x + x1 * wb.x;
        r.y = x0 * wa.y + x1 * wb.y;
        r.z = x0 * wa.z + x1 * wb.z;
        r.w = x0 * wa.w + x1 * wb.w;
        ((float4*)g_A)[idx] = r;
    } else {
        int t = idx - N_PTS * 32;
        if (t < M_PTS * 32) {
            int m = t >> 5, v = t & 31;
            float q0 = qx[2 * m] * S, q1 = qx[2 * m + 1] * S;
            float4 wc = W14[64 + v], wd = W14[96 + v];
            float4 bb = ((const float4*)b1)[v];
            float4 r;
            r.x = q0 * wc.x + q1 * wd.x + bb.x * S;
            r.y = q0 * wc.y + q1 * wd.y + bb.y * S;
            r.z = q0 * wc.z + q1 * wd.z + bb.z * S;
            r.w = q0 * wc.w + q1 * wd.w + bb.w * S;
            ((float4*)g_B)[t] = r;
        }
    }
}

__global__ void prep_y_kernel(const float* __restrict__ qx,
                              const float* __restrict__ ep) {
    __shared__ float red[512];
    int j = threadIdx.x;
    float e = ep[0];
    float y = sinf(PI_F * e * qx[2 * j]) * sinf(PI_F * e * qx[2 * j + 1]);
    g_y[j] = y;
    red[j] = y;
    __syncthreads();
    for (int s = 256; s > 0; s >>= 1) {
        if (j < s) red[j] += red[j + s];
        __syncthreads();
    }
    if (j == 0) g_Y = red[0];
}

// ---------------------------------------------------------------------------
// Main persistent kernel. 256 threads = 8 warps, 3 CTAs/SM.
// Phase 1: thread owns c=lane*4 (A row hoisted); warp w fills j rows w,8+w,...
// GEMM: warp grid 2(m) x 4(n): warp tile = 32 j x 32 k, SINGLE fp16 pass.
// Tail: last CTA (atomic ticket) sums g_part -> out (deterministic order).
// ---------------------------------------------------------------------------
__global__ void __launch_bounds__(256, 3) modnet_mma_kernel(
        const float* __restrict__ W2,
        const float* __restrict__ b2,
        const float* __restrict__ W3,
        const float* __restrict__ b3,
        float* __restrict__ out) {
    extern __shared__ char smem[];
    const uint32_t sb = smem_u32(smem);
    const int tid = threadIdx.x, lane = tid & 31, wid = tid >> 5;
    const int wm = wid & 1, wn = wid >> 1;

    // ---- prologue: W2^T * 2log2e (fp16) into smem ----
    for (int e = tid; e < HID * 64; e += 256) {
        int n = e & 127, cp = e >> 7, c = cp * 2;
        __half2 h = __floats2half2_rn(W2[c * HID + n] * SCALE_2LOG2E,
                                      W2[(c + 1) * HID + n] * SCALE_2LOG2E);
        *(uint32_t*)(smem + SM_W2HI + (uint32_t)(n * PITCH_B + cp * 4)) = h2u(h);
    }
    if (tid < HID) {
        float2 v; v.x = b2[tid] * SCALE_2LOG2E; v.y = W3[tid];
        *(float2*)(smem + SM_B2W3 + tid * 8) = v;
    }
    __syncthreads();

    // lane-invariant ldmatrix addressing
    const uint32_t a_row  = (uint32_t)(wm * 32 + (lane & 15));
    const uint32_t a_coff = (uint32_t)((lane >> 4) * 16);
    const uint32_t aHbase = sb + SM_H1HI + a_row * PITCH_B + a_coff;
    const uint32_t b_n    = (uint32_t)(wn * 32 + ((lane >> 4) << 3) + (lane & 7));
    const uint32_t b_coff = (uint32_t)(((lane >> 3) & 1) * 16);
    const uint32_t bHbase = sb + SM_W2HI + b_n * PITCH_B + b_coff;

    const float2* bw = (const float2*)(smem + SM_B2W3);
    float* red = (float*)(smem + SM_RED);
    const float* ys = (const float*)(smem + SM_YS);

    const int c4 = lane * 4;                 // this thread's column slice
    const uint32_t h1off0 = (uint32_t)(wid * PITCH_B + lane * 8);

    for (int cid = blockIdx.x; cid < NCHUNK; cid += NCTA) {
        const int i  = cid / JT;
        const int j0 = (cid % JT) * TJ;

        // ---- phase 1: h1 = tanh(A_i + B_j) -> fp16 ----
        const float4 a = *(const float4*)(g_A + i * HID + c4);   // hoisted
        #pragma unroll
        for (int it = 0; it < 8; it++) {
            const int j = it * 8 + wid;
            float4 b = *(const float4*)(g_B + (j0 + j) * HID + c4);
            float v0 = tanh_scaled(a.x + b.x);
            float v1 = tanh_scaled(a.y + b.y);
            float v2 = tanh_scaled(a.z + b.z);
            float v3 = tanh_scaled(a.w + b.w);
            uint32_t h0 = h2u(__floats2half2_rn(v0, v1));
            uint32_t h1 = h2u(__floats2half2_rn(v2, v3));
            uint32_t off = h1off0 + (uint32_t)(it * 8 * PITCH_B);
            *(uint2*)(smem + SM_H1HI + off) = make_uint2(h0, h1);
        }
        if (tid < TJ) ((float*)(smem + SM_YS))[tid] = g_y[j0 + tid];
        __syncthreads();

        // ---- phase 2: GEMM, warp tile 32x32, K=128, single fp16 pass ----
        float acc[2][4][4];
        #pragma unroll
        for (int mf = 0; mf < 2; mf++)
            #pragma unroll
            for (int nf = 0; nf < 4; nf++)
                #pragma unroll
                for (int q = 0; q < 4; q++) acc[mf][nf][q] = 0.0f;

        #pragma unroll 2
        for (int ks = 0; ks < 8; ks++) {
            const uint32_t kb = (uint32_t)(ks * 32);
            uint32_t ah[2][4], bh[4][2];
            #pragma unroll
            for (int mf = 0; mf < 2; mf++) {
                uint32_t off = (uint32_t)(mf * 16 * PITCH_B) + kb;
                ldsm4(ah[mf][0], ah[mf][1], ah[mf][2], ah[mf][3], aHbase + off);
            }
            #pragma unroll
            for (int np = 0; np < 2; np++) {
                uint32_t off = (uint32_t)(np * 16 * PITCH_B) + kb;
                ldsm4(bh[np*2][0], bh[np*2][1], bh[np*2+1][0], bh[np*2+1][1],
                      bHbase + off);
            }
            #pragma unroll
            for (int mf = 0; mf < 2; mf++)
                #pragma unroll
                for (int nf = 0; nf < 4; nf++)
                    mma_f16(acc[mf][nf], ah[mf], bh[nf]);
        }

        // ---- phase 3: fused epilogue (acc already scaled by 2log2e) ----
        const int r = lane >> 2, q2 = (lane & 3) * 2;
        float s = 0.0f;
        #pragma unroll
        for (int mf = 0; mf < 2; mf++) {
            const int jr = wm * 32 + mf * 16 + r;
            const float y0 = ys[jr];
            const float y1 = ys[jr + 8];
            #pragma unroll
            for (int nf = 0; nf < 4; nf++) {
                const int k = wn * 32 + nf * 8 + q2;
                float2 c0 = bw[k], c1 = bw[k + 1];
                s += y0 * (tanh_scaled(acc[mf][nf][0] + c0.x) * c0.y
                         + tanh_scaled(acc[mf][nf][1] + c1.x) * c1.y)
                   + y1 * (tanh_scaled(acc[mf][nf][2] + c0.x) * c0.y
                         + tanh_scaled(acc[mf][nf][3] + c1.x) * c1.y);
            }
        }
        #pragma unroll
        for (int o = 16; o > 0; o >>= 1) s += __shfl_xor_sync(0xffffffffu, s, o);
        if (lane == 0) red[wid] = s;
        __syncthreads();
        if (tid == 0) {
            float t = 0.0f;
            #pragma unroll
            for (int w = 0; w < 8; w++) t += red[w];     // fixed order
            g_part[cid] = t;
        }
        __syncthreads();    // red + ys consumed; buffers safe next iteration
    }

    // ---- finalize tail: last CTA to arrive sums g_part -> out ----
    unsigned int* is_last = (unsigned int*)(smem + SM_RED + 32);
    __threadfence();                      // publish g_part before ticket
    __syncthreads();
    if (tid == 0)
        *is_last = (atomicAdd(&g_done, 1u) == (unsigned)(NCTA - 1)) ? 1u : 0u;
    __syncthreads();
    if (*is_last) {
        const float base = b3[0] * g_Y;
        for (int i = tid; i < N_PTS; i += 256) {
            float s2 = base;
            #pragma unroll
            for (int t = 0; t < JT; t++) s2 += g_part[i * JT + t];
            out[i] = s2;
        }
        if (tid == 0) g_done = 0;         // reset: deterministic graph replays
    }
}

// ---------------------------------------------------------------------------
extern "C" void kernel_launch(void* const* d_in, const int* in_sizes, int n_in,
                              void* d_out, int out_size) {
    const float* inp = (const float*)d_in[0];   // [2048, 2]
    const float* qx  = (const float*)d_in[1];   // [512, 2]
    const float* ep  = (const float*)d_in[2];   // [1]
    const float* W1  = (const float*)d_in[3];   // [4, 128]
    const float* b1  = (const float*)d_in[4];   // [128]
    const float* W2  = (const float*)d_in[5];   // [128, 128]
    const float* b2  = (const float*)d_in[6];   // [128]
    const float* W3  = (const float*)d_in[7];   // [128, 1]
    const float* b3  = (const float*)d_in[8];   // [1]
    float* out = (float*)d_out;                 // [2048, 1]
    (void)in_sizes; (void)n_in; (void)out_size;

    cudaFuncSetAttribute(modnet_mma_kernel,
                         cudaFuncAttributeMaxDynamicSharedMemorySize, SMEM_TOTAL);

    prep_ab_kernel<<<(N_PTS * 32 + M_PTS * 32 + 255) / 256, 256>>>(inp, qx, W1, b1);
    prep_y_kernel<<<1, 512>>>(qx, ep);
    modnet_mma_kernel<<<NCTA, 256, SMEM_TOTAL>>>(W2, b2, W3, b3, out);
}

// round 10
// speedup vs baseline: 2.1039x; 1.4617x over previous
#include <cuda_runtime.h>
#include <cuda_fp16.h>
#include <stdint.h>
#include <string.h>

#define N_PTS 2048
#define M_PTS 512
#define HID   128
#define TJ    64                  // j's per chunk
#define JT    (M_PTS / TJ)        // 8 chunks per i
#define NCHUNK (N_PTS * JT)       // 16384
#define NCTA  444                 // 3 per SM
#define PI_F  3.14159265358979323846f

// smem pitch: 136 fp16 per row = 272 B = 17 x 16B -> ldmatrix conflict-free
#define PITCH_B 272

// ---- shared memory layout (bytes) ----
#define SM_W2HI  0                      // [128][136] fp16 (W2^T) 34816 B
#define SM_H1HI  34816                  // [64][136] fp16  17408 B
#define SM_B2W3  52224                  // 128 x float2 (b2, W3)
#define SM_YS    53248                  // 64 floats (y prefetch)
#define SM_RED   53504                  // 8 floats + is_last flag
#define SMEM_TOTAL 53632

// ---- device scratch ----
__device__ __align__(16) float g_A[N_PTS * HID];
__device__ __align__(16) float g_B[M_PTS * HID];
__device__ __align__(16) float g_y[M_PTS];
__device__ float g_Y;
__device__ __align__(16) float g_part[NCHUNK];
__device__ unsigned int g_done;                    // zero-init; reset each run

// ---------------------------------------------------------------------------
__device__ __forceinline__ float tanh_a32(float x) {
    float r;
    asm("tanh.approx.f32 %0, %1;" : "=f"(r) : "f"(x));
    return r;
}

__device__ __forceinline__ uint32_t tanh_a16x2(uint32_t x2) {
    uint32_t r;
    asm("tanh.approx.f16x2 %0, %1;" : "=r"(r) : "r"(x2));
    return r;
}

__device__ __forceinline__ uint32_t smem_u32(const void* p) {
    uint32_t a;
    asm("{ .reg .u64 t; cvta.to.shared.u64 t, %1; cvt.u32.u64 %0, t; }"
        : "=r"(a) : "l"(p));
    return a;
}

__device__ __forceinline__ void ldsm4(uint32_t& r0, uint32_t& r1,
                                      uint32_t& r2, uint32_t& r3, uint32_t addr) {
    asm volatile("ldmatrix.sync.aligned.m8n8.x4.shared.b16 {%0,%1,%2,%3}, [%4];"
                 : "=r"(r0), "=r"(r1), "=r"(r2), "=r"(r3) : "r"(addr));
}

__device__ __forceinline__ void mma_f16(float* d, const uint32_t* a,
                                        const uint32_t* b) {
    asm volatile(
        "mma.sync.aligned.m16n8k16.row.col.f32.f16.f16.f32 "
        "{%0,%1,%2,%3}, {%4,%5,%6,%7}, {%8,%9}, {%0,%1,%2,%3};"
        : "+f"(d[0]), "+f"(d[1]), "+f"(d[2]), "+f"(d[3])
        : "r"(a[0]), "r"(a[1]), "r"(a[2]), "r"(a[3]), "r"(b[0]), "r"(b[1]));
}

__device__ __forceinline__ uint32_t h2u(__half2 h) {
    uint32_t u; memcpy(&u, &h, 4); return u;
}

// ---------------------------------------------------------------------------
// Precompute A[n][h] = input@W1[0:2],  B[m][h] = quad_x@W1[2:4] + b1
// ---------------------------------------------------------------------------
__global__ void prep_ab_kernel(const float* __restrict__ inp,
                               const float* __restrict__ qx,
                               const float* __restrict__ W1,
                               const float* __restrict__ b1) {
    int idx = blockIdx.x * blockDim.x + threadIdx.x;
    const float4* W14 = (const float4*)W1;
    if (idx < N_PTS * 32) {
        int n = idx >> 5, v = idx & 31;
        float x0 = inp[2 * n], x1 = inp[2 * n + 1];
        float4 wa = W14[v], wb = W14[32 + v];
        float4 r;
        r.x = x0 * wa.x + x1 * wb.x;
        r.y = x0 * wa.y + x1 * wb.y;
        r.z = x0 * wa.z + x1 * wb.z;
        r.w = x0 * wa.w + x1 * wb.w;
        ((float4*)g_A)[idx] = r;
    } else {
        int t = idx - N_PTS * 32;
        if (t < M_PTS * 32) {
            int m = t >> 5, v = t & 31;
            float q0 = qx[2 * m], q1 = qx[2 * m + 1];
            float4 wc = W14[64 + v], wd = W14[96 + v];
            float4 bb = ((const float4*)b1)[v];
            float4 r;
            r.x = q0 * wc.x + q1 * wd.x + bb.x;
            r.y = q0 * wc.y + q1 * wd.y + bb.y;
            r.z = q0 * wc.z + q1 * wd.z + bb.z;
            r.w = q0 * wc.w + q1 * wd.w + bb.w;
            ((float4*)g_B)[t] = r;
        }
    }
}

__global__ void prep_y_kernel(const float* __restrict__ qx,
                              const float* __restrict__ ep) {
    __shared__ float red[512];
    int j = threadIdx.x;
    float e = ep[0];
    float y = sinf(PI_F * e * qx[2 * j]) * sinf(PI_F * e * qx[2 * j + 1]);
    g_y[j] = y;
    red[j] = y;
    __syncthreads();
    for (int s = 256; s > 0; s >>= 1) {
        if (j < s) red[j] += red[j + s];
        __syncthreads();
    }
    if (j == 0) g_Y = red[0];
}

// ---------------------------------------------------------------------------
// Main persistent kernel. 256 threads = 8 warps, 3 CTAs/SM.
// Phase 1: tanh.approx.f16x2 (1 MUFU / 2 values, result pre-packed for MMA).
// GEMM: warp grid 2(m) x 4(n): warp tile = 32 j x 32 k, single fp16 pass.
// Epilogue: tanh.approx.f32, fused W3 dot + y-weighted sum.
// Tail: last CTA (atomic ticket) sums g_part -> out (deterministic order).
// ---------------------------------------------------------------------------
__global__ void __launch_bounds__(256, 3) modnet_mma_kernel(
        const float* __restrict__ W2,
        const float* __restrict__ b2,
        const float* __restrict__ W3,
        const float* __restrict__ b3,
        float* __restrict__ out) {
    extern __shared__ char smem[];
    const uint32_t sb = smem_u32(smem);
    const int tid = threadIdx.x, lane = tid & 31, wid = tid >> 5;
    const int wm = wid & 1, wn = wid >> 1;

    // ---- prologue: W2^T (fp16) into smem ----
    for (int e = tid; e < HID * 64; e += 256) {
        int n = e & 127, cp = e >> 7, c = cp * 2;
        __half2 h = __floats2half2_rn(W2[c * HID + n], W2[(c + 1) * HID + n]);
        *(uint32_t*)(smem + SM_W2HI + (uint32_t)(n * PITCH_B + cp * 4)) = h2u(h);
    }
    if (tid < HID) {
        float2 v; v.x = b2[tid]; v.y = W3[tid];
        *(float2*)(smem + SM_B2W3 + tid * 8) = v;
    }
    __syncthreads();

    // lane-invariant ldmatrix addressing
    const uint32_t a_row  = (uint32_t)(wm * 32 + (lane & 15));
    const uint32_t a_coff = (uint32_t)((lane >> 4) * 16);
    const uint32_t aHbase = sb + SM_H1HI + a_row * PITCH_B + a_coff;
    const uint32_t b_n    = (uint32_t)(wn * 32 + ((lane >> 4) << 3) + (lane & 7));
    const uint32_t b_coff = (uint32_t)(((lane >> 3) & 1) * 16);
    const uint32_t bHbase = sb + SM_W2HI + b_n * PITCH_B + b_coff;

    const float2* bw = (const float2*)(smem + SM_B2W3);
    float* red = (float*)(smem + SM_RED);
    const float* ys = (const float*)(smem + SM_YS);

    const int c4 = lane * 4;                 // this thread's column slice
    const uint32_t h1off0 = (uint32_t)(wid * PITCH_B + lane * 8);

    for (int cid = blockIdx.x; cid < NCHUNK; cid += NCTA) {
        const int i  = cid / JT;
        const int j0 = (cid % JT) * TJ;

        // ---- phase 1: h1 = tanh(A_i + B_j) via tanh.approx.f16x2 ----
        const float4 a = *(const float4*)(g_A + i * HID + c4);   // hoisted
        #pragma unroll
        for (int it = 0; it < 8; it++) {
            const int j = it * 8 + wid;
            float4 b = *(const float4*)(g_B + (j0 + j) * HID + c4);
            uint32_t x01 = h2u(__floats2half2_rn(a.x + b.x, a.y + b.y));
            uint32_t x23 = h2u(__floats2half2_rn(a.z + b.z, a.w + b.w));
            uint32_t t01 = tanh_a16x2(x01);
            uint32_t t23 = tanh_a16x2(x23);
            uint32_t off = h1off0 + (uint32_t)(it * 8 * PITCH_B);
            *(uint2*)(smem + SM_H1HI + off) = make_uint2(t01, t23);
        }
        if (tid < TJ) ((float*)(smem + SM_YS))[tid] = g_y[j0 + tid];
        __syncthreads();

        // ---- phase 2: GEMM, warp tile 32x32, K=128, single fp16 pass ----
        float acc[2][4][4];
        #pragma unroll
        for (int mf = 0; mf < 2; mf++)
            #pragma unroll
            for (int nf = 0; nf < 4; nf++)
                #pragma unroll
                for (int q = 0; q < 4; q++) acc[mf][nf][q] = 0.0f;

        #pragma unroll 2
        for (int ks = 0; ks < 8; ks++) {
            const uint32_t kb = (uint32_t)(ks * 32);
            uint32_t ah[2][4], bh[4][2];
            #pragma unroll
            for (int mf = 0; mf < 2; mf++) {
                uint32_t off = (uint32_t)(mf * 16 * PITCH_B) + kb;
                ldsm4(ah[mf][0], ah[mf][1], ah[mf][2], ah[mf][3], aHbase + off);
            }
            #pragma unroll
            for (int np = 0; np < 2; np++) {
                uint32_t off = (uint32_t)(np * 16 * PITCH_B) + kb;
                ldsm4(bh[np*2][0], bh[np*2][1], bh[np*2+1][0], bh[np*2+1][1],
                      bHbase + off);
            }
            #pragma unroll
            for (int mf = 0; mf < 2; mf++)
                #pragma unroll
                for (int nf = 0; nf < 4; nf++)
                    mma_f16(acc[mf][nf], ah[mf], bh[nf]);
        }

        // ---- phase 3: fused epilogue (tanh.approx.f32) ----
        const int r = lane >> 2, q2 = (lane & 3) * 2;
        float s = 0.0f;
        #pragma unroll
        for (int mf = 0; mf < 2; mf++) {
            const int jr = wm * 32 + mf * 16 + r;
            const float y0 = ys[jr];
            const float y1 = ys[jr + 8];
            #pragma unroll
            for (int nf = 0; nf < 4; nf++) {
                const int k = wn * 32 + nf * 8 + q2;
                float2 c0 = bw[k], c1 = bw[k + 1];
                s += y0 * (tanh_a32(acc[mf][nf][0] + c0.x) * c0.y
                         + tanh_a32(acc[mf][nf][1] + c1.x) * c1.y)
                   + y1 * (tanh_a32(acc[mf][nf][2] + c0.x) * c0.y
                         + tanh_a32(acc[mf][nf][3] + c1.x) * c1.y);
            }
        }
        #pragma unroll
        for (int o = 16; o > 0; o >>= 1) s += __shfl_xor_sync(0xffffffffu, s, o);
        if (lane == 0) red[wid] = s;
        __syncthreads();
        if (tid == 0) {
            float t = 0.0f;
            #pragma unroll
            for (int w = 0; w < 8; w++) t += red[w];     // fixed order
            g_part[cid] = t;
        }
        __syncthreads();    // red + ys consumed; buffers safe next iteration
    }

    // ---- finalize tail: last CTA to arrive sums g_part -> out ----
    unsigned int* is_last = (unsigned int*)(smem + SM_RED + 32);
    __threadfence();                      // publish g_part before ticket
    __syncthreads();
    if (tid == 0)
        *is_last = (atomicAdd(&g_done, 1u) == (unsigned)(NCTA - 1)) ? 1u : 0u;
    __syncthreads();
    if (*is_last) {
        const float base = b3[0] * g_Y;
        for (int i = tid; i < N_PTS; i += 256) {
            float s2 = base;
            #pragma unroll
            for (int t = 0; t < JT; t++) s2 += g_part[i * JT + t];
            out[i] = s2;
        }
        if (tid == 0) g_done = 0;         // reset: deterministic graph replays
    }
}

// ---------------------------------------------------------------------------
extern "C" void kernel_launch(void* const* d_in, const int* in_sizes, int n_in,
                              void* d_out, int out_size) {
    const float* inp = (const float*)d_in[0];   // [2048, 2]
    const float* qx  = (const float*)d_in[1];   // [512, 2]
    const float* ep  = (const float*)d_in[2];   // [1]
    const float* W1  = (const float*)d_in[3];   // [4, 128]
    const float* b1  = (const float*)d_in[4];   // [128]
    const float* W2  = (const float*)d_in[5];   // [128, 128]
    const float* b2  = (const float*)d_in[6];   // [128]
    const float* W3  = (const float*)d_in[7];   // [128, 1]
    const float* b3  = (const float*)d_in[8];   // [1]
    float* out = (float*)d_out;                 // [2048, 1]
    (void)in_sizes; (void)n_in; (void)out_size;

    cudaFuncSetAttribute(modnet_mma_kernel,
                         cudaFuncAttributeMaxDynamicSharedMemorySize, SMEM_TOTAL);

    prep_ab_kernel<<<(N_PTS * 32 + M_PTS * 32 + 255) / 256, 256>>>(inp, qx, W1, b1);
    prep_y_kernel<<<1, 512>>>(qx, ep);
    modnet_mma_kernel<<<NCTA, 256, SMEM_TOTAL>>>(W2, b2, W3, b3, out);
}